// round 11
// baseline (speedup 1.0000x reference)
#include <cuda_runtime.h>
#include <cstdint>

#define BATCH 8
#define NROI 2000
#define NCLS 81
#define NCLS1 (NCLS - 1)
#define MAXDET 100
#define META_W (12 + NCLS)
#define CAP 128
#define ARR 2048
#define ROIS_PER_BLK 8

typedef unsigned long long u64;
#define KMAX 0xFFFFFFFFFFFFFFFFull
#define SENT43 ((1ull << 43) - 1)
#define SUPBIT (1ull << 63)

// ---------------- device scratch (zero-initialized at load) -----------------
__device__ float4 g_box[BATCH][NROI];
__device__ u64    g_lists[BATCH][NCLS1][CAP];
__device__ int    g_cnt[BATCH][NCLS1];   // reset by class_nms after read
__device__ u64    g_karr[BATCH][ARR];    // compact kept keys per batch
__device__ int    g_kc[BATCH];           // kept count; reset by select at end

__device__ __forceinline__ unsigned int f2ord(float s) {
    unsigned int u = __float_as_uint(s);
    return (u & 0x80000000u) ? ~u : (u | 0x80000000u);
}
__device__ __forceinline__ float ord2f(unsigned int o) {
    unsigned int u = (o & 0x80000000u) ? (o ^ 0x80000000u) : ~o;
    return __uint_as_float(u);
}

// ============================= Kernel 1: refine + bucket =====================
__global__ __launch_bounds__(ROIS_PER_BLK * 32)
void refine_kernel(const float* __restrict__ rois,
                   const float* __restrict__ probs,
                   const float* __restrict__ deltas,
                   const float* __restrict__ meta) {
    const int blk  = blockIdx.x;
    const int b    = blk / (NROI / ROIS_PER_BLK);
    const int rblk = blk % (NROI / ROIS_PER_BLK);
    const int warp = threadIdx.x >> 5;
    const int lane = threadIdx.x & 31;
    const int r    = rblk * ROIS_PER_BLK + warp;

    const float* p = probs + ((size_t)b * NROI + r) * NCLS;
    // local 3-way pick (first occurrence => strict >, increasing ci order)
    float v = p[lane];
    int ci = lane;
    {
        float v2 = p[lane + 32];
        if (v2 > v) { v = v2; ci = lane + 32; }
        if (lane + 64 < NCLS) {
            float v3 = p[lane + 64];
            if (v3 > v) { v = v3; ci = lane + 64; }
        }
    }
    // softmax scores >= 0 -> float bits are uint-monotonic
    unsigned fb = __float_as_uint(v);
    unsigned m = __reduce_max_sync(0xffffffffu, fb);
    unsigned cisel = (fb == m) ? (unsigned)ci : 0xFFFFFFFFu;
    unsigned cmin = __reduce_min_sync(0xffffffffu, cisel);

    if (lane == 0) {
        v = __uint_as_float(m);
        ci = (int)cmin;

        float h = meta[4], w = meta[5];
        float sy = h - 1.0f, sx = w - 1.0f;
        const float* mw = meta + (size_t)b * META_W + 7;
        float wy1 = mw[0] / sy;
        float wx1 = mw[1] / sx;
        float wy2 = (mw[2] - 1.0f) / sy;
        float wx2 = (mw[3] - 1.0f) / sx;

        float4 roi = *reinterpret_cast<const float4*>(rois + ((size_t)b * NROI + r) * 4);
        float4 d   = *reinterpret_cast<const float4*>(deltas + (((size_t)b * NROI + r) * NCLS + ci) * 4);
        d.x *= 0.1f; d.y *= 0.1f; d.z *= 0.2f; d.w *= 0.2f;
        float hh = roi.z - roi.x;
        float ww = roi.w - roi.y;
        float cy = roi.x + 0.5f * hh + d.x * hh;
        float cx = roi.y + 0.5f * ww + d.y * ww;
        hh *= expf(d.z);
        ww *= expf(d.w);
        float y1 = cy - 0.5f * hh;
        float x1 = cx - 0.5f * ww;
        float y2 = y1 + hh;
        float x2 = x1 + ww;
        y1 = fminf(fmaxf(y1, wy1), wy2);
        x1 = fminf(fmaxf(x1, wx1), wx2);
        y2 = fminf(fmaxf(y2, wy1), wy2);
        x2 = fminf(fmaxf(x2, wx1), wx2);

        g_box[b][r] = make_float4(y1, x1, y2, x2);
        if ((ci > 0) && (v >= 0.7f)) {
            unsigned int desc = ~f2ord(v);
            u64 k = (((u64)desc) << 11) | (unsigned int)r;
            int pos = atomicAdd(&g_cnt[b][ci - 1], 1);
            if (pos < CAP) g_lists[b][ci - 1][pos] = k;
        }
    }
}

// ============================= Kernel 2: per-class NMS =======================
// One warp per (batch, class): load, warp-sort, greedy NMS, append compact kept.
__global__ __launch_bounds__(128)
void class_nms_kernel() {
    __shared__ u64    lists[4][CAP];
    __shared__ float4 sbox[4][CAP];
    const int wib  = threadIdx.x >> 5;
    const int lane = threadIdx.x & 31;
    const int g    = blockIdx.x * 4 + wib;
    const int b    = g / NCLS1;
    const int c    = g % NCLS1;               // 0-based; class id = c+1
    u64* row = lists[wib];
    float4* sb = sbox[wib];
    const unsigned lmask = (1u << lane) - 1u;

    int n = g_cnt[b][c];
    if (lane == 0) g_cnt[b][c] = 0;            // restore invariant (unique reader)
    if (n > CAP) n = CAP;
    for (int i = lane; i < n; i += 32) row[i] = g_lists[b][c][i];
    __syncwarp();

    if (n > 1) {
        int P = 2;
        while (P < n) P <<= 1;
        for (int t = n + lane; t < P; t += 32) row[t] = SENT43;
        __syncwarp();
        // warp bitonic: ascending masked key = (score desc, idx asc)
        for (int k2 = 2; k2 <= P; k2 <<= 1) {
            for (int j = k2 >> 1; j > 0; j >>= 1) {
                for (int i0 = 0; i0 < P; i0 += 32) {
                    int i = i0 + lane;
                    int ixj = i ^ j;
                    if (i < P && ixj > i && ixj < P) {
                        u64 a = row[i];
                        u64 bb = row[ixj];
                        bool up = ((i & k2) == 0);
                        if ((a > bb) == up) { row[i] = bb; row[ixj] = a; }
                    }
                }
                __syncwarp();
            }
        }
        for (int i = lane; i < n; i += 32)
            sb[i] = g_box[b][(int)(row[i] & 0x7FFu)];
        __syncwarp();
        for (int i = 0; i < n; ++i) {
            u64 ki = row[i];
            if (ki & SUPBIT) continue;
            float4 bi = sb[i];
            float areai = (bi.z - bi.x) * (bi.w - bi.y);
            for (int j = i + 1 + lane; j < n; j += 32) {
                u64 kj = row[j];
                if (kj & SUPBIT) continue;
                float4 bj = sb[j];
                float ih = fmaxf(fminf(bi.z, bj.z) - fmaxf(bi.x, bj.x), 0.0f);
                float iw = fmaxf(fminf(bi.w, bj.w) - fmaxf(bi.y, bj.y), 0.0f);
                float inter = ih * iw;
                float areaj = (bj.z - bj.x) * (bj.w - bj.y);
                float uni = areai + areaj - inter;
                if (inter / (uni + 1e-8f) > 0.3f) row[j] = kj | SUPBIT;
            }
            __syncwarp();
        }
    }

    // count kept, reserve contiguous slot in g_karr[b], append
    int kn = 0;
    for (int t0 = 0; t0 < n; t0 += 32) {
        int t = t0 + lane;
        u64 k = (t < n) ? row[t] : SUPBIT;
        kn += __popc(__ballot_sync(0xffffffffu, (t < n) && !(k & SUPBIT)));
    }
    if (kn == 0) return;
    int base = 0;
    if (lane == 0) base = atomicAdd(&g_kc[b], kn);
    base = __shfl_sync(0xffffffffu, base, 0);
    int wr = 0;
    for (int t0 = 0; t0 < n; t0 += 32) {
        int t = t0 + lane;
        u64 k = (t < n) ? row[t] : SUPBIT;
        bool live = (t < n) && !(k & SUPBIT);
        unsigned ball = __ballot_sync(0xffffffffu, live);
        if (live) {
            int p = base + wr + __popc(ball & lmask);
            if (p < ARR) g_karr[b][p] = (k << 7) | (unsigned)(c + 1);
        }
        wr += __popc(ball);
    }
}

// ============================= Kernel 3: rank-select + emit ==================
// sk = masked43<<7 | cls. Keys unique -> ranks are a permutation.
__global__ __launch_bounds__(1024)
void select_kernel(float* __restrict__ out) {
    __shared__ u64 arr[ARR];
    __shared__ u64 sel[MAXDET];

    const int b = blockIdx.x;
    const int tid = threadIdx.x;

    if (tid < MAXDET) sel[tid] = KMAX;

    int K = g_kc[b];
    if (K > ARR) K = ARR;
    // coalesced gather of compact kept keys
    for (int t = tid; t < K; t += 1024) arr[t] = g_karr[b][t];
    __syncthreads();
    if (tid == 0) g_kc[b] = 0;                 // restore invariant (last reader)

    // rank-select: position = #(smaller keys). LDS-broadcast inner loop.
    for (int e = tid; e < K; e += 1024) {
        u64 ke = arr[e];
        int rank = 0;
        for (int j = 0; j < K; ++j)
            rank += (arr[j] < ke) ? 1 : 0;
        if (rank < MAXDET) sel[rank] = ke;
    }
    __syncthreads();

    // emit 100 x 6
    float* ob = out + (size_t)b * MAXDET * 6;
    for (int t = tid; t < MAXDET * 6; t += 1024) {
        int row = t / 6;
        int col = t - row * 6;
        u64 sv = sel[row];
        float val = 0.0f;
        if (sv != KMAX) {
            int idx = (int)((sv >> 7) & 0x7FFu);
            if (col < 4) {
                float4 bx = g_box[b][idx];
                val = (col == 0) ? bx.x : (col == 1) ? bx.y : (col == 2) ? bx.z : bx.w;
            } else if (col == 4) {
                val = (float)((int)(sv & 0x7Fu));
            } else {
                unsigned int desc = (unsigned int)((sv >> 18) & 0xFFFFFFFFull);
                val = ord2f(~desc);
            }
        }
        ob[t] = val;
    }
}

extern "C" void kernel_launch(void* const* d_in, const int* in_sizes, int n_in,
                              void* d_out, int out_size) {
    const float* rois   = (const float*)d_in[0];
    const float* probs  = (const float*)d_in[1];
    const float* deltas = (const float*)d_in[2];
    const float* meta   = (const float*)d_in[3];
    float* out = (float*)d_out;

    refine_kernel<<<BATCH * (NROI / ROIS_PER_BLK), ROIS_PER_BLK * 32>>>(rois, probs, deltas, meta);
    class_nms_kernel<<<BATCH * NCLS1 / 4, 128>>>();
    select_kernel<<<BATCH, 1024>>>(out);
}

// round 12
// speedup vs baseline: 1.8122x; 1.8122x over previous
#include <cuda_runtime.h>
#include <cstdint>

#define BATCH 8
#define NROI 2000
#define NCLS 81
#define NCLS1 (NCLS - 1)
#define MAXDET 100
#define META_W (12 + NCLS)
#define CAP 128
#define ARR 2048
#define ROIS_PER_BLK 8
#define FULLM 0xffffffffu

typedef unsigned long long u64;
#define KMAX 0xFFFFFFFFFFFFFFFFull
#define SENT43 ((1ull << 43) - 1)
#define SUPBIT (1ull << 63)

// ---------------- device scratch (zero-initialized at load) -----------------
__device__ float4 g_box[BATCH][NROI];          // valid ROIs only (emit path)
__device__ u64    g_lkey[BATCH][NCLS1][CAP];   // per-class candidate keys
__device__ float4 g_lboxv[BATCH][NCLS1][CAP];  // per-class candidate boxes
__device__ int    g_cnt[BATCH][NCLS1];         // reset by class_nms after read
__device__ u64    g_karr[BATCH][ARR];          // compact kept keys per batch
__device__ int    g_kc[BATCH];                 // kept count; reset by select

__device__ __forceinline__ unsigned int f2ord(float s) {
    unsigned int u = __float_as_uint(s);
    return (u & 0x80000000u) ? ~u : (u | 0x80000000u);
}
__device__ __forceinline__ float ord2f(unsigned int o) {
    unsigned int u = (o & 0x80000000u) ? (o ^ 0x80000000u) : ~o;
    return __uint_as_float(u);
}

// ============================= Kernel 1: refine + bucket =====================
__global__ __launch_bounds__(ROIS_PER_BLK * 32)
void refine_kernel(const float* __restrict__ rois,
                   const float* __restrict__ probs,
                   const float* __restrict__ deltas,
                   const float* __restrict__ meta) {
    const int blk  = blockIdx.x;
    const int b    = blk / (NROI / ROIS_PER_BLK);
    const int rblk = blk % (NROI / ROIS_PER_BLK);
    const int warp = threadIdx.x >> 5;
    const int lane = threadIdx.x & 31;
    const int r    = rblk * ROIS_PER_BLK + warp;

    const float* p = probs + ((size_t)b * NROI + r) * NCLS;
    float v = p[lane];
    int ci = lane;
    {
        float v2 = p[lane + 32];
        if (v2 > v) { v = v2; ci = lane + 32; }
        if (lane + 64 < NCLS) {
            float v3 = p[lane + 64];
            if (v3 > v) { v = v3; ci = lane + 64; }
        }
    }
    // softmax scores >= 0 -> float bits uint-monotonic; first-occurrence argmax
    unsigned fb = __float_as_uint(v);
    unsigned m = __reduce_max_sync(FULLM, fb);
    unsigned cisel = (fb == m) ? (unsigned)ci : 0xFFFFFFFFu;
    unsigned cmin = __reduce_min_sync(FULLM, cisel);

    if (lane == 0) {
        v = __uint_as_float(m);
        ci = (int)cmin;
        if ((ci > 0) && (v >= 0.7f)) {
            float h = meta[4], w = meta[5];
            float sy = h - 1.0f, sx = w - 1.0f;
            const float* mw = meta + (size_t)b * META_W + 7;
            float wy1 = mw[0] / sy;
            float wx1 = mw[1] / sx;
            float wy2 = (mw[2] - 1.0f) / sy;
            float wx2 = (mw[3] - 1.0f) / sx;

            float4 roi = *reinterpret_cast<const float4*>(rois + ((size_t)b * NROI + r) * 4);
            float4 d   = *reinterpret_cast<const float4*>(deltas + (((size_t)b * NROI + r) * NCLS + ci) * 4);
            d.x *= 0.1f; d.y *= 0.1f; d.z *= 0.2f; d.w *= 0.2f;
            float hh = roi.z - roi.x;
            float ww = roi.w - roi.y;
            float cy = roi.x + 0.5f * hh + d.x * hh;
            float cx = roi.y + 0.5f * ww + d.y * ww;
            hh *= expf(d.z);
            ww *= expf(d.w);
            float y1 = cy - 0.5f * hh;
            float x1 = cx - 0.5f * ww;
            float y2 = y1 + hh;
            float x2 = x1 + ww;
            y1 = fminf(fmaxf(y1, wy1), wy2);
            x1 = fminf(fmaxf(x1, wx1), wx2);
            y2 = fminf(fmaxf(y2, wy1), wy2);
            x2 = fminf(fmaxf(x2, wx1), wx2);
            float4 bx = make_float4(y1, x1, y2, x2);

            g_box[b][r] = bx;
            unsigned int desc = ~f2ord(v);
            u64 k = (((u64)desc) << 11) | (unsigned int)r;
            int pos = atomicAdd(&g_cnt[b][ci - 1], 1);
            if (pos < CAP) {
                g_lkey[b][ci - 1][pos]  = k;
                g_lboxv[b][ci - 1][pos] = bx;
            }
        }
    }
}

// ============================= Kernel 2: per-class NMS =======================
__global__ __launch_bounds__(128)
void class_nms_kernel() {
    __shared__ u64    lists[4][CAP];
    __shared__ float4 sboxs[4][CAP];
    const int wib  = threadIdx.x >> 5;
    const int lane = threadIdx.x & 31;
    const int g    = blockIdx.x * 4 + wib;
    const int b    = g / NCLS1;
    const int c    = g % NCLS1;               // 0-based; class id = c+1
    const unsigned lmask = (1u << lane) - 1u;

    int n = g_cnt[b][c];
    if (lane == 0) g_cnt[b][c] = 0;            // restore invariant (unique reader)
    if (n > CAP) n = CAP;
    if (n == 0) return;

    if (n <= 32) {
        // --------- register-resident fast path ---------
        u64 kv = KMAX;
        float4 bx = make_float4(0.f, 0.f, 0.f, 0.f);
        if (lane < n) {
            kv = (g_lkey[b][c][lane] << 5) | (unsigned)lane;   // key(43b)<<5 | srclane
            bx = g_lboxv[b][c][lane];
        }
        // warp bitonic sort ascending on kv (key unique -> exact (score desc, idx asc))
#pragma unroll
        for (int k2 = 2; k2 <= 32; k2 <<= 1) {
#pragma unroll
            for (int j = k2 >> 1; j > 0; j >>= 1) {
                u64 other = __shfl_xor_sync(FULLM, kv, j);
                bool up = ((lane & k2) == 0);
                bool lower = ((lane & j) == 0);
                bool keepMin = (up == lower);
                bool take = keepMin ? (other < kv) : (other > kv);
                if (take) kv = other;
            }
        }
        // permute boxes to sorted order
        int src = (int)(kv & 31u);
        float4 sb;
        sb.x = __shfl_sync(FULLM, bx.x, src);
        sb.y = __shfl_sync(FULLM, bx.y, src);
        sb.z = __shfl_sync(FULLM, bx.z, src);
        sb.w = __shfl_sync(FULLM, bx.w, src);
        u64 key = kv >> 5;                       // masked43 (pads -> huge)
        float area = (sb.z - sb.x) * (sb.w - sb.y);
        bool alive = (lane < n);

        for (int i = 0; i < n; ++i) {
            unsigned am = __ballot_sync(FULLM, alive);
            if (!((am >> i) & 1u)) continue;     // uniform
            float iy1 = __shfl_sync(FULLM, sb.x, i);
            float ix1 = __shfl_sync(FULLM, sb.y, i);
            float iy2 = __shfl_sync(FULLM, sb.z, i);
            float ix2 = __shfl_sync(FULLM, sb.w, i);
            float ai  = __shfl_sync(FULLM, area, i);
            if (alive && lane > i) {
                float ih = fmaxf(fminf(iy2, sb.z) - fmaxf(iy1, sb.x), 0.0f);
                float iw = fmaxf(fminf(ix2, sb.w) - fmaxf(ix1, sb.y), 0.0f);
                float inter = ih * iw;
                float uni = ai + area - inter;
                if (inter / (uni + 1e-8f) > 0.3f) alive = false;
            }
        }
        unsigned am = __ballot_sync(FULLM, alive);
        int kn = __popc(am);
        if (kn == 0) return;
        int base = 0;
        if (lane == 0) base = atomicAdd(&g_kc[b], kn);
        base = __shfl_sync(FULLM, base, 0);
        if (alive) {
            int p = base + __popc(am & lmask);
            if (p < ARR) g_karr[b][p] = (key << 7) | (unsigned)(c + 1);
        }
        return;
    }

    // --------- smem fallback path (n > 32, rare) ---------
    u64* row = lists[wib];
    float4* sbp = sboxs[wib];
    for (int i = lane; i < n; i += 32) row[i] = g_lkey[b][c][i];
    __syncwarp();
    {
        int P = 2;
        while (P < n) P <<= 1;
        for (int t = n + lane; t < P; t += 32) row[t] = SENT43;
        __syncwarp();
        for (int k2 = 2; k2 <= P; k2 <<= 1) {
            for (int j = k2 >> 1; j > 0; j >>= 1) {
                for (int i0 = 0; i0 < P; i0 += 32) {
                    int i = i0 + lane;
                    int ixj = i ^ j;
                    if (i < P && ixj > i && ixj < P) {
                        u64 a = row[i];
                        u64 bb = row[ixj];
                        bool up = ((i & k2) == 0);
                        if ((a > bb) == up) { row[i] = bb; row[ixj] = a; }
                    }
                }
                __syncwarp();
            }
        }
        for (int i = lane; i < n; i += 32)
            sbp[i] = g_box[b][(int)(row[i] & 0x7FFu)];
        __syncwarp();
        for (int i = 0; i < n; ++i) {
            u64 ki = row[i];
            if (ki & SUPBIT) continue;
            float4 bi = sbp[i];
            float areai = (bi.z - bi.x) * (bi.w - bi.y);
            for (int j = i + 1 + lane; j < n; j += 32) {
                u64 kj = row[j];
                if (kj & SUPBIT) continue;
                float4 bj = sbp[j];
                float ih = fmaxf(fminf(bi.z, bj.z) - fmaxf(bi.x, bj.x), 0.0f);
                float iw = fmaxf(fminf(bi.w, bj.w) - fmaxf(bi.y, bj.y), 0.0f);
                float inter = ih * iw;
                float areaj = (bj.z - bj.x) * (bj.w - bj.y);
                float uni = areai + areaj - inter;
                if (inter / (uni + 1e-8f) > 0.3f) row[j] = kj | SUPBIT;
            }
            __syncwarp();
        }
    }
    int kn = 0;
    for (int t0 = 0; t0 < n; t0 += 32) {
        int t = t0 + lane;
        u64 k = (t < n) ? row[t] : SUPBIT;
        kn += __popc(__ballot_sync(FULLM, (t < n) && !(k & SUPBIT)));
    }
    if (kn == 0) return;
    int base = 0;
    if (lane == 0) base = atomicAdd(&g_kc[b], kn);
    base = __shfl_sync(FULLM, base, 0);
    int wr = 0;
    for (int t0 = 0; t0 < n; t0 += 32) {
        int t = t0 + lane;
        u64 k = (t < n) ? row[t] : SUPBIT;
        bool live = (t < n) && !(k & SUPBIT);
        unsigned ball = __ballot_sync(FULLM, live);
        if (live) {
            int p = base + wr + __popc(ball & lmask);
            if (p < ARR) g_karr[b][p] = (k << 7) | (unsigned)(c + 1);
        }
        wr += __popc(ball);
    }
}

// ============================= Kernel 3: radix-select + emit =================
// sk = masked43<<7 | cls; desc(score) = sk bits [49:18]. Scores in [0.7,1.0]
// => desc byte3 constant -> 2 radix rounds (shifts 34, 26) suffice to shrink.
__global__ __launch_bounds__(1024)
void select_kernel(float* __restrict__ out) {
    __shared__ u64 arr[ARR];
    __shared__ u64 Lk[ARR];
    __shared__ unsigned short candA[ARR];
    __shared__ unsigned short candB[ARR];
    __shared__ unsigned short acc[ARR];
    __shared__ int bins[256];
    __shared__ u64 sel[MAXDET];
    __shared__ int naccS, ncandNextS, tbinS, doneS;

    const int b = blockIdx.x;
    const int tid = threadIdx.x;
    const int lane = tid & 31;
    const int warp = tid >> 5;

    if (tid == 0) { naccS = 0; doneS = 0; }
    if (tid < MAXDET) sel[tid] = KMAX;

    int K = g_kc[b];
    if (K > ARR) K = ARR;
    for (int t = tid; t < K; t += 1024) arr[t] = g_karr[b][t];
    __syncthreads();
    if (tid == 0) g_kc[b] = 0;                 // restore invariant (last reader)

    int ncand;
    if (K <= MAXDET) {
        for (int t = tid; t < K; t += 1024) acc[t] = (unsigned short)t;
        if (tid == 0) naccS = K;
        ncand = 0;
        __syncthreads();
    } else {
        for (int t = tid; t < K; t += 1024) candA[t] = (unsigned short)t;
        ncand = K;
        __syncthreads();

        const int shifts[2] = {34, 26};
#pragma unroll
        for (int rnd = 0; rnd < 2; ++rnd) {
            if (doneS) break;
            int shift = shifts[rnd];
            if (tid < 256) bins[tid] = 0;
            if (tid == 0) ncandNextS = 0;
            __syncthreads();
            for (int i = tid; i < ncand; i += 1024) {
                int bin = (int)((arr[candA[i]] >> shift) & 0xFF);
                atomicAdd(&bins[bin], 1);
            }
            __syncthreads();
            if (warp == 0) {
                int need = MAXDET - naccS;
                int carry = 0;
                int tbin = 255;
                bool found = false;
#pragma unroll
                for (int ch = 0; ch < 8; ++ch) {
                    int v = bins[ch * 32 + lane];
                    int incl = v;
#pragma unroll
                    for (int o = 1; o < 32; o <<= 1) {
                        int x = __shfl_up_sync(FULLM, incl, o);
                        if (lane >= o) incl += x;
                    }
                    int cum = carry + incl;
                    unsigned ball = __ballot_sync(FULLM, cum >= need);
                    if (!found && ball) {
                        tbin = ch * 32 + (__ffs(ball) - 1);
                        found = true;
                    }
                    carry = __shfl_sync(FULLM, carry + incl, 31);
                }
                if (lane == 0) tbinS = tbin;
            }
            __syncthreads();
            int tbin = tbinS;
            for (int i = tid; i < ncand; i += 1024) {
                unsigned short idx = candA[i];
                int bin = (int)((arr[idx] >> shift) & 0xFF);
                if (bin < tbin) {
                    acc[atomicAdd(&naccS, 1)] = idx;
                } else if (bin == tbin) {
                    candB[atomicAdd(&ncandNextS, 1)] = idx;
                }
            }
            __syncthreads();
            ncand = ncandNextS;
            for (int i = tid; i < ncand; i += 1024) candA[i] = candB[i];
            if (tid == 0 && naccS + ncand <= MAXDET) doneS = 1;
            __syncthreads();
        }
    }

    // finalists -> exact top-100 via rank select
    int nacc = naccS;
    int nL = nacc + ncand;
    if (nL > ARR) nL = ARR;
    for (int t = tid; t < nL; t += 1024)
        Lk[t] = arr[(t < nacc) ? acc[t] : candA[t - nacc]];
    __syncthreads();

    for (int e = tid; e < nL; e += 1024) {
        u64 ke = Lk[e];
        int rank = 0;
        for (int j = 0; j < nL; ++j)
            rank += (Lk[j] < ke) ? 1 : 0;
        if (rank < MAXDET) sel[rank] = ke;
    }
    __syncthreads();

    // emit 100 x 6
    float* ob = out + (size_t)b * MAXDET * 6;
    for (int t = tid; t < MAXDET * 6; t += 1024) {
        int row = t / 6;
        int col = t - row * 6;
        u64 sv = sel[row];
        float val = 0.0f;
        if (sv != KMAX) {
            int idx = (int)((sv >> 7) & 0x7FFu);
            if (col < 4) {
                float4 bx = g_box[b][idx];
                val = (col == 0) ? bx.x : (col == 1) ? bx.y : (col == 2) ? bx.z : bx.w;
            } else if (col == 4) {
                val = (float)((int)(sv & 0x7Fu));
            } else {
                unsigned int desc = (unsigned int)((sv >> 18) & 0xFFFFFFFFull);
                val = ord2f(~desc);
            }
        }
        ob[t] = val;
    }
}

extern "C" void kernel_launch(void* const* d_in, const int* in_sizes, int n_in,
                              void* d_out, int out_size) {
    const float* rois   = (const float*)d_in[0];
    const float* probs  = (const float*)d_in[1];
    const float* deltas = (const float*)d_in[2];
    const float* meta   = (const float*)d_in[3];
    float* out = (float*)d_out;

    refine_kernel<<<BATCH * (NROI / ROIS_PER_BLK), ROIS_PER_BLK * 32>>>(rois, probs, deltas, meta);
    class_nms_kernel<<<BATCH * NCLS1 / 4, 128>>>();
    select_kernel<<<BATCH, 1024>>>(out);
}